// round 10
// baseline (speedup 1.0000x reference)
#include <cuda_runtime.h>
#include <cstdint>
#include <float.h>

#define NB    4
#define NPTS  8192
#define NPQ   2048
#define NCH   128

// ---------------- device scratch (statically allocated; no cudaMalloc) ----------------
__device__ float4 g_p4[NB * NPTS];                    // (x,y,z,|p|^2) original order
__device__ float4 g_ps[NB * NPTS];                    // points sorted by 16^3 cell
__device__ float4 g_q4[NB * NPQ];                     // sampled points
__device__ int    g_fps[NB * NPQ];
__device__ int    g_ord[NB * NPTS];                   // sorted slot -> original index
__device__ int    g_pcs[NB][4097];                    // point-grid cell starts (morton 16^3)
__device__ int    g_nbr[NB * NPQ * 16];               // kNN indices (ranks 1..16, ascending)
__device__ float  g_feat_t[(size_t)NB * NPTS * NCH];  // features transposed [B,N,C]
__device__ float  g_coarse_t[(size_t)NB * NPQ * NCH]; // pooled features [B,q,C]
__device__ int    g_i3[NB * NPTS * 3];
__device__ float  g_w3[NB * NPTS * 3];
// three_nn sample-grid structures
__device__ float4 g_qs[NB * NPQ];                     // samples sorted by 8^3 cell
__device__ int    g_qj[NB * NPQ];                     // original sample index j
__device__ int    g_cs[NB][513];                      // sample cell starts (8^3 grid)
__device__ float  g_bb[NB][8];                        // x0,y0,z0, 8/sx,8/sy,8/sz, hmin8, hmin16

typedef unsigned long long u64;

// ---------------- packed f32x2 helpers ----------------
__device__ __forceinline__ u64 pk2(float a, float b) {
    u64 r; asm("mov.b64 %0, {%1,%2};" : "=l"(r) : "f"(a), "f"(b)); return r;
}
__device__ __forceinline__ void upk2(u64 v, float& a, float& b) {
    asm("mov.b64 {%0,%1}, %2;" : "=f"(a), "=f"(b) : "l"(v));
}
__device__ __forceinline__ u64 add2(u64 a, u64 b) {
    u64 r; asm("add.rn.f32x2 %0, %1, %2;" : "=l"(r) : "l"(a), "l"(b)); return r;
}
__device__ __forceinline__ u64 mul2(u64 a, u64 b) {
    u64 r; asm("mul.rn.f32x2 %0, %1, %2;" : "=l"(r) : "l"(a), "l"(b)); return r;
}
__device__ __forceinline__ u64 fma2(u64 a, u64 b, u64 c) {
    u64 r; asm("fma.rn.f32x2 %0, %1, %2, %3;" : "=l"(r) : "l"(a), "l"(b), "l"(c)); return r;
}

// ---------------- prep: pack points + squared norm ----------------
__global__ void prep_kernel(const float* __restrict__ pts) {
    int i = blockIdx.x * 256 + threadIdx.x;          // over NB*NPTS
    float x = pts[3 * i], y = pts[3 * i + 1], z = pts[3 * i + 2];
    float nr = __fmaf_rn(z, z, __fmaf_rn(y, y, x * x));
    g_p4[i] = make_float4(x, y, z, nr);
}

// ---------------- per-batch bbox (deterministic block reduce) ----------------
__global__ void __launch_bounds__(256) bbox_kernel() {
    __shared__ float s[6][256];
    int b = blockIdx.x, t = threadIdx.x;
    float lx = FLT_MAX, hx = -FLT_MAX, ly = FLT_MAX, hy = -FLT_MAX,
          lz = FLT_MAX, hz = -FLT_MAX;
    for (int i = t; i < NPTS; i += 256) {
        float4 p = g_p4[b * NPTS + i];
        lx = fminf(lx, p.x); hx = fmaxf(hx, p.x);
        ly = fminf(ly, p.y); hy = fmaxf(hy, p.y);
        lz = fminf(lz, p.z); hz = fmaxf(hz, p.z);
    }
    s[0][t] = lx; s[1][t] = hx; s[2][t] = ly; s[3][t] = hy; s[4][t] = lz; s[5][t] = hz;
    __syncthreads();
    for (int o = 128; o > 0; o >>= 1) {
        if (t < o) {
            s[0][t] = fminf(s[0][t], s[0][t + o]);
            s[1][t] = fmaxf(s[1][t], s[1][t + o]);
            s[2][t] = fminf(s[2][t], s[2][t + o]);
            s[3][t] = fmaxf(s[3][t], s[3][t + o]);
            s[4][t] = fminf(s[4][t], s[4][t + o]);
            s[5][t] = fmaxf(s[5][t], s[5][t + o]);
        }
        __syncthreads();
    }
    if (t == 0) {
        float sx = (s[1][0] - s[0][0]) * 1.000001f + 1e-30f;
        float sy = (s[3][0] - s[2][0]) * 1.000001f + 1e-30f;
        float sz = (s[5][0] - s[4][0]) * 1.000001f + 1e-30f;
        g_bb[b][0] = s[0][0]; g_bb[b][1] = s[2][0]; g_bb[b][2] = s[4][0];
        g_bb[b][3] = 8.f / sx; g_bb[b][4] = 8.f / sy; g_bb[b][5] = 8.f / sz;
        float mn = fminf(fminf(sx, sy), sz);
        g_bb[b][6] = mn * 0.125f  * 0.999f;   // conservative hmin, 8^3 sample grid
        g_bb[b][7] = mn * 0.0625f * 0.999f;   // conservative hmin, 16^3 point grid
    }
}

// ---------------- transpose features [B,C,N] -> [B,N,C] ----------------
__global__ void transpose_kernel(const float* __restrict__ f) {
    __shared__ float tile[32][33];
    int b = blockIdx.z;
    int c0 = blockIdx.y * 32, n0 = blockIdx.x * 32;
    tile[threadIdx.y][threadIdx.x] =
        f[((size_t)b * NCH + c0 + threadIdx.y) * NPTS + n0 + threadIdx.x];
    __syncthreads();
    g_feat_t[((size_t)b * NPTS + n0 + threadIdx.y) * NCH + c0 + threadIdx.x] =
        tile[threadIdx.x][threadIdx.y];
}

// ---------------- point binning: counting sort into 16^3 morton cells over bbox ----------------
__device__ __forceinline__ unsigned eb4(unsigned v) {  // 4 bits -> stride-3 positions
    return (v & 1u) | ((v & 2u) << 2) | ((v & 4u) << 4) | ((v & 8u) << 6);
}
__global__ void __launch_bounds__(1024, 1) sort_kernel() {
    __shared__ unsigned hist[4096];
    __shared__ unsigned wsum[32];
    const int b = blockIdx.x, tid = threadIdx.x;
    const int lane = tid & 31, wid = tid >> 5;
    for (int i = tid; i < 4096; i += 1024) hist[i] = 0;
    __syncthreads();
    float x0 = g_bb[b][0], y0 = g_bb[b][1], z0 = g_bb[b][2];
    float ix = g_bb[b][3] * 2.f, iy = g_bb[b][4] * 2.f, iz = g_bb[b][5] * 2.f;
    float4 p[8]; unsigned code[8];
#pragma unroll
    for (int k = 0; k < 8; k++) {
        int i = tid + k * 1024;
        p[k] = g_p4[b * NPTS + i];
        unsigned mx = (unsigned)min(15, max(0, (int)((p[k].x - x0) * ix)));
        unsigned my = (unsigned)min(15, max(0, (int)((p[k].y - y0) * iy)));
        unsigned mz = (unsigned)min(15, max(0, (int)((p[k].z - z0) * iz)));
        code[k] = eb4(mx) | (eb4(my) << 1) | (eb4(mz) << 2);
        atomicAdd(&hist[code[k]], 1u);
    }
    __syncthreads();
    unsigned h0 = hist[4 * tid], h1 = hist[4 * tid + 1],
             h2 = hist[4 * tid + 2], h3 = hist[4 * tid + 3];
    unsigned s = h0 + h1 + h2 + h3, si = s;
#pragma unroll
    for (int d = 1; d < 32; d <<= 1) {
        unsigned v = __shfl_up_sync(0xffffffffu, si, d);
        if (lane >= d) si += v;
    }
    if (lane == 31) wsum[wid] = si;
    __syncthreads();
    if (wid == 0) {
        unsigned v = wsum[lane], vi = v;
#pragma unroll
        for (int d = 1; d < 32; d <<= 1) {
            unsigned t = __shfl_up_sync(0xffffffffu, vi, d);
            if (lane >= d) vi += t;
        }
        wsum[lane] = vi;
    }
    __syncthreads();
    unsigned base = (wid ? wsum[wid - 1] : 0u) + si - s;
    hist[4 * tid]     = base;
    hist[4 * tid + 1] = base + h0;
    hist[4 * tid + 2] = base + h0 + h1;
    hist[4 * tid + 3] = base + h0 + h1 + h2;
    // publish cell starts
    g_pcs[b][4 * tid]     = base;
    g_pcs[b][4 * tid + 1] = base + h0;
    g_pcs[b][4 * tid + 2] = base + h0 + h1;
    g_pcs[b][4 * tid + 3] = base + h0 + h1 + h2;
    if (tid == 0) g_pcs[b][4096] = NPTS;
    __syncthreads();
#pragma unroll
    for (int k = 0; k < 8; k++) {
        int i = tid + k * 1024;
        unsigned slot = atomicAdd(&hist[code[k]], 1u);
        g_ord[b * NPTS + slot] = i;
        g_ps[b * NPTS + slot]  = p[k];
    }
}

// ---------------- FPS: one CTA/batch, warp pruning, 1 barrier/iter ----------------
// Update math = reference's EXACT subtract-form fma chain (frozen). Prune
// margin wmax*1.00001 conservative. Tie rule = lowest original index.
__global__ void __launch_bounds__(1024, 1) fps_kernel() {
    extern __shared__ char fsmem[];                   // sP 128KB | sOrd 32KB
    float4* sP   = (float4*)fsmem;
    int*    sOrd = (int*)(fsmem + NPTS * sizeof(float4));
    const int b    = blockIdx.x;
    const int tid  = threadIdx.x;
    const int lane = tid & 31;
    const int wid  = tid >> 5;
    const float4* __restrict__ P = g_p4 + b * NPTS;

#pragma unroll
    for (int k = 0; k < 8; k++) {
        sP[tid + k * 1024]   = P[tid + k * 1024];
        sOrd[tid + k * 1024] = g_ord[b * NPTS + tid + k * 1024];
    }
    __shared__ u64 skey[2][32];
    if (tid == 0) g_fps[b * NPQ] = 0;
    __syncthreads();

    const int wbase = wid * 256 + lane * 2;
    u64 X[4], Y[4], Z[4];
    float dist[8];
    unsigned ordp[4];                                 // 2x16b packed original indices
    float blx = FLT_MAX, bhx = -FLT_MAX, bly = FLT_MAX, bhy = -FLT_MAX,
          blz = FLT_MAX, bhz = -FLT_MAX;
#pragma unroll
    for (int i = 0; i < 4; i++) {
        int o0 = sOrd[wbase + i * 64], o1 = sOrd[wbase + i * 64 + 1];
        ordp[i] = (unsigned)o0 | ((unsigned)o1 << 16);
        float4 a = sP[o0], c = sP[o1];
        X[i] = pk2(a.x, c.x); Y[i] = pk2(a.y, c.y); Z[i] = pk2(a.z, c.z);
        blx = fminf(blx, fminf(a.x, c.x)); bhx = fmaxf(bhx, fmaxf(a.x, c.x));
        bly = fminf(bly, fminf(a.y, c.y)); bhy = fmaxf(bhy, fmaxf(a.y, c.y));
        blz = fminf(blz, fminf(a.z, c.z)); bhz = fmaxf(bhz, fmaxf(a.z, c.z));
    }
#pragma unroll
    for (int s = 16; s > 0; s >>= 1) {
        blx = fminf(blx, __shfl_xor_sync(0xffffffffu, blx, s));
        bhx = fmaxf(bhx, __shfl_xor_sync(0xffffffffu, bhx, s));
        bly = fminf(bly, __shfl_xor_sync(0xffffffffu, bly, s));
        bhy = fmaxf(bhy, __shfl_xor_sync(0xffffffffu, bhy, s));
        blz = fminf(blz, __shfl_xor_sync(0xffffffffu, blz, s));
        bhz = fmaxf(bhz, __shfl_xor_sync(0xffffffffu, bhz, s));
    }

    u64 mykey;
    float wmaxf;
    {   // iteration 0: d0 = ||x - x0||^2
        float4 q0 = sP[0];
        u64 ax = pk2(-q0.x, -q0.x), ay = pk2(-q0.y, -q0.y), az = pk2(-q0.z, -q0.z);
#pragma unroll
        for (int i = 0; i < 4; i++) {
            u64 dx = add2(X[i], ax), dy = add2(Y[i], ay), dz = add2(Z[i], az);
            u64 t = fma2(dz, dz, fma2(dy, dy, mul2(dx, dx)));
            upk2(t, dist[2 * i], dist[2 * i + 1]);
        }
        float tmax = fmaxf(fmaxf(fmaxf(dist[0], dist[1]), fmaxf(dist[2], dist[3])),
                           fmaxf(fmaxf(dist[4], dist[5]), fmaxf(dist[6], dist[7])));
        unsigned wm = __reduce_max_sync(0xffffffffu, __float_as_uint(tmax));
        wmaxf = __uint_as_float(wm);
        unsigned cand = 0xffffffffu;
#pragma unroll
        for (int k = 0; k < 8; k++) {
            unsigned oi = (k & 1) ? (ordp[k >> 1] >> 16) : (ordp[k >> 1] & 0xffffu);
            if (dist[k] == wmaxf) cand = min(cand, oi);
        }
        unsigned widx = __reduce_min_sync(0xffffffffu, cand);
        mykey = ((u64)wm << 32) | widx;
        if (lane == 0) skey[0][wid] = mykey;
    }

    for (int j = 1; j < NPQ; j++) {
        __syncthreads();                               // prev-iter keys visible
        u64 k64 = skey[(j - 1) & 1][lane];
        unsigned hi = (unsigned)(k64 >> 32), lo = (unsigned)k64;
        unsigned g   = __reduce_max_sync(0xffffffffu, hi);
        unsigned cc  = (hi == g) ? lo : 0xffffffffu;
        unsigned nxt = __reduce_min_sync(0xffffffffu, cc);
        if (tid == 0) g_fps[b * NPQ + j] = (int)nxt;

        float4 qq = sP[nxt];                           // LDS broadcast
        float dxb = fmaxf(fmaxf(blx - qq.x, qq.x - bhx), 0.f);
        float dyb = fmaxf(fmaxf(bly - qq.y, qq.y - bhy), 0.f);
        float dzb = fmaxf(fmaxf(blz - qq.z, qq.z - bhz), 0.f);
        float boxd2 = __fmaf_rn(dzb, dzb, __fmaf_rn(dyb, dyb, dxb * dxb));

        if (boxd2 < wmaxf * 1.00001f) {                // conservative: update
            u64 ax = pk2(-qq.x, -qq.x), ay = pk2(-qq.y, -qq.y), az = pk2(-qq.z, -qq.z);
#pragma unroll
            for (int i = 0; i < 4; i++) {
                u64 dx = add2(X[i], ax), dy = add2(Y[i], ay), dz = add2(Z[i], az);
                u64 t = fma2(dz, dz, fma2(dy, dy, mul2(dx, dx)));
                float a, c; upk2(t, a, c);
                dist[2 * i]     = fminf(dist[2 * i], a);
                dist[2 * i + 1] = fminf(dist[2 * i + 1], c);
            }
            float tmax = fmaxf(fmaxf(fmaxf(dist[0], dist[1]), fmaxf(dist[2], dist[3])),
                               fmaxf(fmaxf(dist[4], dist[5]), fmaxf(dist[6], dist[7])));
            unsigned wm = __reduce_max_sync(0xffffffffu, __float_as_uint(tmax));
            wmaxf = __uint_as_float(wm);
            unsigned cand = 0xffffffffu;
#pragma unroll
            for (int k = 0; k < 8; k++) {
                unsigned oi = (k & 1) ? (ordp[k >> 1] >> 16) : (ordp[k >> 1] & 0xffffu);
                if (dist[k] == wmaxf) cand = min(cand, oi);
            }
            unsigned widx = __reduce_min_sync(0xffffffffu, cand);
            mykey = ((u64)wm << 32) | widx;
        }
        if (lane == 0) skey[j & 1][wid] = mykey;       // always post
    }
}

// ---------------- gather sampled coords ----------------
__global__ void gather_q4_kernel() {
    int i = blockIdx.x * 256 + threadIdx.x;          // over NB*NPQ
    int b = i >> 11;
    g_q4[i] = g_p4[b * NPTS + g_fps[i]];
}

// ---------------- bucket samples into 8^3 grid (counting sort) ----------------
__global__ void __launch_bounds__(256) bucket_kernel() {
    __shared__ unsigned hist[512];
    __shared__ unsigned wsum[8];
    const int b = blockIdx.x, t = threadIdx.x;
    const int lane = t & 31, wid = t >> 5;
    hist[t] = 0; hist[t + 256] = 0;
    __syncthreads();
    float4 q[8]; int cell[8];
    float x0 = g_bb[b][0], y0 = g_bb[b][1], z0 = g_bb[b][2];
    float ix = g_bb[b][3], iy = g_bb[b][4], iz = g_bb[b][5];
#pragma unroll
    for (int k = 0; k < 8; k++) {
        int i = t + k * 256;
        q[k] = g_q4[b * NPQ + i];
        int cx = min(7, max(0, (int)((q[k].x - x0) * ix)));
        int cy = min(7, max(0, (int)((q[k].y - y0) * iy)));
        int cz = min(7, max(0, (int)((q[k].z - z0) * iz)));
        cell[k] = (cz * 8 + cy) * 8 + cx;
        atomicAdd(&hist[cell[k]], 1u);
    }
    __syncthreads();
    unsigned h0 = hist[2 * t], h1 = hist[2 * t + 1];
    unsigned s = h0 + h1, si = s;
#pragma unroll
    for (int d = 1; d < 32; d <<= 1) {
        unsigned v = __shfl_up_sync(0xffffffffu, si, d);
        if (lane >= d) si += v;
    }
    if (lane == 31) wsum[wid] = si;
    __syncthreads();
    if (t < 32) {
        unsigned v = (t < 8) ? wsum[t] : 0u, vi = v;
#pragma unroll
        for (int d = 1; d < 32; d <<= 1) {
            unsigned w2 = __shfl_up_sync(0xffffffffu, vi, d);
            if (t >= d) vi += w2;
        }
        if (t < 8) wsum[t] = vi;
    }
    __syncthreads();
    unsigned base = (wid ? wsum[wid - 1] : 0u) + si - s;
    hist[2 * t] = base; hist[2 * t + 1] = base + h0;
    g_cs[b][2 * t] = base; g_cs[b][2 * t + 1] = base + h0;
    if (t == 0) g_cs[b][512] = NPQ;
    __syncthreads();
#pragma unroll
    for (int k = 0; k < 8; k++) {
        int i = t + k * 256;
        unsigned slot = atomicAdd(&hist[cell[k]], 1u);
        g_qs[b * NPQ + slot] = q[k];
        g_qj[b * NPQ + slot] = i;
    }
}

// ---------------- kNN indices via point grid: per-thread sorted top-17 ----------------
// Exact same candidate math as brute force (identical fma chain); lex keys
// (sqbits, origidx) = top_k tie rule; ring bound k[16] < (r*hmin16)^2 is
// strictly conservative -> top-17 set identical to full scan.
__global__ void __launch_bounds__(256) knn_idx_kernel() {
    int b = blockIdx.y;
    int t = blockIdx.x * 256 + threadIdx.x;           // sorted-sample slot
    float4 q = g_qs[b * NPQ + t];
    int jq = g_qj[b * NPQ + t];
    float x0 = g_bb[b][0], y0 = g_bb[b][1], z0 = g_bb[b][2];
    float ix = g_bb[b][3] * 2.f, iy = g_bb[b][4] * 2.f, iz = g_bb[b][5] * 2.f;
    float hp = g_bb[b][7];
    int cx = min(15, max(0, (int)((q.x - x0) * ix)));
    int cy = min(15, max(0, (int)((q.y - y0) * iy)));
    int cz = min(15, max(0, (int)((q.z - z0) * iz)));
    const int*    cs = g_pcs[b];
    const float4* PS = g_ps + b * NPTS;
    const int*    PO = g_ord + b * NPTS;

    u64 k[17];
#pragma unroll
    for (int i = 0; i < 17; i++) k[i] = ~0ull;

    for (int r = 0; r < 16; r++) {
        int xl = max(cx - r, 0), xh = min(cx + r, 15);
        int yl = max(cy - r, 0), yh = min(cy + r, 15);
        int zl = max(cz - r, 0), zh = min(cz + r, 15);
        for (int zz = zl; zz <= zh; zz++)
            for (int yy = yl; yy <= yh; yy++)
                for (int xx = xl; xx <= xh; xx++) {
                    int ring = max(max(abs(xx - cx), abs(yy - cy)), abs(zz - cz));
                    if (ring != r) continue;
                    unsigned mc = eb4((unsigned)xx) | (eb4((unsigned)yy) << 1)
                                | (eb4((unsigned)zz) << 2);
                    int e = cs[mc + 1];
                    for (int s = cs[mc]; s < e; s++) {
                        float4 p = PS[s];
                        float dot = __fmaf_rn(q.z, p.z, __fmaf_rn(q.y, p.y, q.x * p.x));
                        float sq  = fmaxf(__fmaf_rn(-2.f, dot, q.w + p.w), 0.f);
                        u64 key = ((u64)__float_as_uint(sq) << 32) | (unsigned)PO[s];
                        if (key < k[16]) {
                            k[16] = key;
#pragma unroll
                            for (int ii = 16; ii > 0; ii--) {
                                u64 a = k[ii - 1], c = k[ii];
                                bool sw = c < a;
                                k[ii - 1] = sw ? c : a;
                                k[ii]     = sw ? a : c;
                            }
                        }
                    }
                }
        float br = (float)r * hp;                     // rings > r have dist >= (r*hp)^2
        if (k[16] < ((u64)__float_as_uint(br * br) << 32)) break;
    }

    int ob = (b * NPQ + jq) * 16;                     // ranks 1..16 (skip self)
#pragma unroll
    for (int r = 1; r < 17; r++) g_nbr[ob + r - 1] = (int)(unsigned)k[r];
}

// ---------------- kNN mean-pool: warp per query, ascending-distance order ----------------
__global__ void __launch_bounds__(256) knn_pool_kernel() {
    int gw   = blockIdx.x * 8 + (threadIdx.x >> 5);   // global query id
    int lane = threadIdx.x & 31;
    int b    = gw >> 11;
    const float* Fb = g_feat_t + (size_t)b * NPTS * NCH;
    const int* nb = g_nbr + (size_t)gw * 16;
    float4 acc = make_float4(0.f, 0.f, 0.f, 0.f);
#pragma unroll 1
    for (int r = 0; r < 16; r++) {
        int nn = nb[r];
        float4 f = ((const float4*)(Fb + (size_t)nn * NCH))[lane];
        acc.x += f.x; acc.y += f.y; acc.z += f.z; acc.w += f.w;
    }
    float4 o = make_float4(acc.x * 0.0625f, acc.y * 0.0625f,
                           acc.z * 0.0625f, acc.w * 0.0625f);
    ((float4*)(g_coarse_t + (size_t)gw * NCH))[lane] = o;
}

// ---------------- three_nn via sample grid: ring search, lex top-3 ----------------
__global__ void __launch_bounds__(256) three_nn_kernel() {
    int b   = blockIdx.y;
    int gid = blockIdx.x * 256 + threadIdx.x;
    int n   = g_ord[b * NPTS + gid];                  // cell order -> warp convergence
    float4 p = g_p4[b * NPTS + n];
    float x0 = g_bb[b][0], y0 = g_bb[b][1], z0 = g_bb[b][2];
    float ix = g_bb[b][3], iy = g_bb[b][4], iz = g_bb[b][5];
    float hmin = g_bb[b][6];
    int cx = min(7, max(0, (int)((p.x - x0) * ix)));
    int cy = min(7, max(0, (int)((p.y - y0) * iy)));
    int cz = min(7, max(0, (int)((p.z - z0) * iz)));
    const int*    cs = g_cs[b];
    const float4* QS = g_qs + b * NPQ;
    const int*    QJ = g_qj + b * NPQ;

    u64 k0 = ~0ull, k1 = ~0ull, k2 = ~0ull;
    for (int r = 0; r < 8; r++) {
        int xl = max(cx - r, 0), xh = min(cx + r, 7);
        int yl = max(cy - r, 0), yh = min(cy + r, 7);
        int zl = max(cz - r, 0), zh = min(cz + r, 7);
        for (int zz = zl; zz <= zh; zz++)
            for (int yy = yl; yy <= yh; yy++)
                for (int xx = xl; xx <= xh; xx++) {
                    int ring = max(max(abs(xx - cx), abs(yy - cy)), abs(zz - cz));
                    if (ring != r) continue;
                    int cell = (zz * 8 + yy) * 8 + xx;
                    for (int t = cs[cell]; t < cs[cell + 1]; t++) {
                        float4 q = QS[t];
                        float dot = __fmaf_rn(q.z, p.z, __fmaf_rn(q.y, p.y, q.x * p.x));
                        float s   = fmaxf(__fmaf_rn(-2.f, dot, q.w + p.w), 0.f);
                        u64 key = ((u64)__float_as_uint(s) << 32) | (unsigned)QJ[t];
                        if (key < k2) {
                            if (key < k0)      { k2 = k1; k1 = k0; k0 = key; }
                            else if (key < k1) { k2 = k1; k1 = key; }
                            else               { k2 = key; }
                        }
                    }
                }
        float br = (float)r * hmin;                   // rings > r have dist >= (r*hmin)^2
        if (k2 < ((u64)__float_as_uint(br * br) << 32)) break;
    }

    float d0 = fmaxf(__uint_as_float((unsigned)(k0 >> 32)), 1e-10f);
    float d1 = fmaxf(__uint_as_float((unsigned)(k1 >> 32)), 1e-10f);
    float d2 = fmaxf(__uint_as_float((unsigned)(k2 >> 32)), 1e-10f);
    float v0 = __fdiv_rn(1.f, d0 + 1e-8f);
    float v1 = __fdiv_rn(1.f, d1 + 1e-8f);
    float v2 = __fdiv_rn(1.f, d2 + 1e-8f);
    float ss = v0 + v1 + v2;
    int o = (b * NPTS + n) * 3;
    g_i3[o] = (int)(unsigned)k0; g_i3[o + 1] = (int)(unsigned)k1; g_i3[o + 2] = (int)(unsigned)k2;
    g_w3[o]     = __fdiv_rn(v0, ss);
    g_w3[o + 1] = __fdiv_rn(v1, ss);
    g_w3[o + 2] = __fdiv_rn(v2, ss);
}

// ---------------- interpolate: out[b,c,n] = sum_k w_k * coarse[b, i3_k, c] ----------------
__global__ void __launch_bounds__(256) interp_kernel(float* __restrict__ out) {
    int b    = blockIdx.y;
    int n    = blockIdx.x * 8 + threadIdx.y;
    int lane = threadIdx.x;
    int o = (b * NPTS + n) * 3;
    int a0 = g_i3[o], a1 = g_i3[o + 1], a2 = g_i3[o + 2];
    float w0 = g_w3[o], w1 = g_w3[o + 1], w2 = g_w3[o + 2];

    const float4* C = (const float4*)g_coarse_t + (size_t)b * NPQ * (NCH / 4);
    float4 f0 = C[a0 * (NCH / 4) + lane];
    float4 f1 = C[a1 * (NCH / 4) + lane];
    float4 f2 = C[a2 * (NCH / 4) + lane];

    float4 r;
    r.x = __fmaf_rn(f2.x, w2, __fmaf_rn(f1.x, w1, f0.x * w0));
    r.y = __fmaf_rn(f2.y, w2, __fmaf_rn(f1.y, w1, f0.y * w0));
    r.z = __fmaf_rn(f2.z, w2, __fmaf_rn(f1.z, w1, f0.z * w0));
    r.w = __fmaf_rn(f2.w, w2, __fmaf_rn(f1.w, w1, f0.w * w0));

    float* op = out + (size_t)b * NCH * NPTS + n;
    int c = lane * 4;
    op[(size_t)(c + 0) * NPTS] = r.x;
    op[(size_t)(c + 1) * NPTS] = r.y;
    op[(size_t)(c + 2) * NPTS] = r.z;
    op[(size_t)(c + 3) * NPTS] = r.w;
}

// ---------------- launch ----------------
extern "C" void kernel_launch(void* const* d_in, const int* in_sizes, int n_in,
                              void* d_out, int out_size) {
    const float* points   = (const float*)d_in[0];
    const float* features = (const float*)d_in[1];
    for (int i = 0; i < n_in; i++) {
        if (in_sizes[i] == NB * NPTS * 3)            points   = (const float*)d_in[i];
        else if (in_sizes[i] == NB * NCH * NPTS)     features = (const float*)d_in[i];
    }
    float* out = (float*)d_out;

    const int fps_smem = NPTS * (int)sizeof(float4) + NPTS * (int)sizeof(int); // 160KB
    cudaFuncSetAttribute(fps_kernel, cudaFuncAttributeMaxDynamicSharedMemorySize, fps_smem);

    prep_kernel<<<(NB * NPTS) / 256, 256>>>(points);
    bbox_kernel<<<NB, 256>>>();
    transpose_kernel<<<dim3(NPTS / 32, NCH / 32, NB), dim3(32, 32)>>>(features);
    sort_kernel<<<NB, 1024>>>();
    fps_kernel<<<NB, 1024, fps_smem>>>();
    gather_q4_kernel<<<(NB * NPQ) / 256, 256>>>();
    bucket_kernel<<<NB, 256>>>();
    knn_idx_kernel<<<dim3(NPQ / 256, NB), 256>>>();
    knn_pool_kernel<<<(NB * NPQ) / 8, 256>>>();
    three_nn_kernel<<<dim3(NPTS / 256, NB), 256>>>();
    interp_kernel<<<dim3(NPTS / 8, NB), dim3(32, 8)>>>(out);
}

// round 11
// speedup vs baseline: 1.2129x; 1.2129x over previous
#include <cuda_runtime.h>
#include <cstdint>
#include <float.h>

#define NB    4
#define NPTS  8192
#define NPQ   2048
#define NCH   128

// ---------------- device scratch (statically allocated; no cudaMalloc) ----------------
__device__ float4 g_p4[NB * NPTS];                    // (x,y,z,|p|^2)
__device__ float4 g_q4[NB * NPQ];                     // sampled points
__device__ int    g_fps[NB * NPQ];
__device__ int    g_ord[NB * NPTS];                   // morton-binned original indices
__device__ float  g_feat_t[(size_t)NB * NPTS * NCH];  // features transposed [B,N,C]
__device__ float  g_coarse_t[(size_t)NB * NPQ * NCH]; // pooled features [B,q,C]
__device__ int    g_i3[NB * NPTS * 3];
__device__ float  g_w3[NB * NPTS * 3];

typedef unsigned long long u64;
__device__ u64 g_nn[(size_t)NB * NPTS * 12];          // three_nn partials: 4 chunks x 3 keys

// ---------------- packed f32x2 helpers ----------------
__device__ __forceinline__ u64 pk2(float a, float b) {
    u64 r; asm("mov.b64 %0, {%1,%2};" : "=l"(r) : "f"(a), "f"(b)); return r;
}
__device__ __forceinline__ void upk2(u64 v, float& a, float& b) {
    asm("mov.b64 {%0,%1}, %2;" : "=f"(a), "=f"(b) : "l"(v));
}
__device__ __forceinline__ u64 add2(u64 a, u64 b) {
    u64 r; asm("add.rn.f32x2 %0, %1, %2;" : "=l"(r) : "l"(a), "l"(b)); return r;
}
__device__ __forceinline__ u64 mul2(u64 a, u64 b) {
    u64 r; asm("mul.rn.f32x2 %0, %1, %2;" : "=l"(r) : "l"(a), "l"(b)); return r;
}
__device__ __forceinline__ u64 fma2(u64 a, u64 b, u64 c) {
    u64 r; asm("fma.rn.f32x2 %0, %1, %2, %3;" : "=l"(r) : "l"(a), "l"(b), "l"(c)); return r;
}

// ---------------- prep: pack points + squared norm ----------------
__global__ void prep_kernel(const float* __restrict__ pts) {
    int i = blockIdx.x * 256 + threadIdx.x;          // over NB*NPTS
    float x = pts[3 * i], y = pts[3 * i + 1], z = pts[3 * i + 2];
    float nr = __fmaf_rn(z, z, __fmaf_rn(y, y, x * x));
    g_p4[i] = make_float4(x, y, z, nr);
}

// ---------------- transpose features [B,C,N] -> [B,N,C] ----------------
__global__ void transpose_kernel(const float* __restrict__ f) {
    __shared__ float tile[32][33];
    int b = blockIdx.z;
    int c0 = blockIdx.y * 32, n0 = blockIdx.x * 32;
    tile[threadIdx.y][threadIdx.x] =
        f[((size_t)b * NCH + c0 + threadIdx.y) * NPTS + n0 + threadIdx.x];
    __syncthreads();
    g_feat_t[((size_t)b * NPTS + n0 + threadIdx.y) * NCH + c0 + threadIdx.x] =
        tile[threadIdx.x][threadIdx.y];
}

// ---------------- morton binning: counting sort into 4096 cells (16^3) ----------------
__device__ __forceinline__ unsigned eb4(unsigned v) {  // 4 bits -> stride-3 positions
    return (v & 1u) | ((v & 2u) << 2) | ((v & 4u) << 4) | ((v & 8u) << 6);
}
__global__ void __launch_bounds__(1024, 1) sort_kernel() {
    __shared__ unsigned hist[4096];
    __shared__ unsigned wsum[32];
    const int b = blockIdx.x, tid = threadIdx.x;
    const int lane = tid & 31, wid = tid >> 5;
    for (int i = tid; i < 4096; i += 1024) hist[i] = 0;
    __syncthreads();
    unsigned code[8];
#pragma unroll
    for (int k = 0; k < 8; k++) {
        int i = tid + k * 1024;
        float4 p = g_p4[b * NPTS + i];
        unsigned mx = (unsigned)fminf(fmaxf((p.x + 4.f) * 2.f, 0.f), 15.f);
        unsigned my = (unsigned)fminf(fmaxf((p.y + 4.f) * 2.f, 0.f), 15.f);
        unsigned mz = (unsigned)fminf(fmaxf((p.z + 4.f) * 2.f, 0.f), 15.f);
        code[k] = eb4(mx) | (eb4(my) << 1) | (eb4(mz) << 2);
        atomicAdd(&hist[code[k]], 1u);
    }
    __syncthreads();
    unsigned h0 = hist[4 * tid], h1 = hist[4 * tid + 1],
             h2 = hist[4 * tid + 2], h3 = hist[4 * tid + 3];
    unsigned s = h0 + h1 + h2 + h3, si = s;
#pragma unroll
    for (int d = 1; d < 32; d <<= 1) {
        unsigned v = __shfl_up_sync(0xffffffffu, si, d);
        if (lane >= d) si += v;
    }
    if (lane == 31) wsum[wid] = si;
    __syncthreads();
    if (wid == 0) {
        unsigned v = wsum[lane], vi = v;
#pragma unroll
        for (int d = 1; d < 32; d <<= 1) {
            unsigned t = __shfl_up_sync(0xffffffffu, vi, d);
            if (lane >= d) vi += t;
        }
        wsum[lane] = vi;
    }
    __syncthreads();
    unsigned base = (wid ? wsum[wid - 1] : 0u) + si - s;
    hist[4 * tid]     = base;
    hist[4 * tid + 1] = base + h0;
    hist[4 * tid + 2] = base + h0 + h1;
    hist[4 * tid + 3] = base + h0 + h1 + h2;
    __syncthreads();
#pragma unroll
    for (int k = 0; k < 8; k++) {
        int i = tid + k * 1024;
        unsigned slot = atomicAdd(&hist[code[k]], 1u);
        g_ord[b * NPTS + slot] = i;
    }
}

// ---------------- FPS: one CTA/batch, 512 threads x 16 pts, warp pruning ----------------
// Head redundancy halved vs 1024-thread variant (fps is head-bound: every warp
// redundantly computes nxt). Update math = reference's EXACT subtract-form fma
// chain (frozen). Prune margin wmax*1.00001 conservative. Tie rule = lowest
// original index (jnp.argmax first-occurrence).
__global__ void __launch_bounds__(512, 1) fps_kernel() {
    extern __shared__ char fsmem[];                   // sP 128KB | sOrd 32KB
    float4* sP   = (float4*)fsmem;
    int*    sOrd = (int*)(fsmem + NPTS * sizeof(float4));
    const int b    = blockIdx.x;
    const int tid  = threadIdx.x;
    const int lane = tid & 31;
    const int wid  = tid >> 5;                        // 0..15
    const float4* __restrict__ P = g_p4 + b * NPTS;

#pragma unroll
    for (int k = 0; k < 16; k++) {
        sP[tid + k * 512]   = P[tid + k * 512];
        sOrd[tid + k * 512] = g_ord[b * NPTS + tid + k * 512];
    }
    __shared__ u64 skey[2][16];
    if (tid == 0) g_fps[b * NPQ] = 0;
    __syncthreads();

    // warp owns sorted range [wid*512, wid*512+512); pair i covers 64-pt span
    const int wbase = wid * 512 + lane * 2;
    u64 X[8], Y[8], Z[8];
    float dist[16];
    unsigned ordp[8];                                 // 2x16b packed original indices
    float blx = FLT_MAX, bhx = -FLT_MAX, bly = FLT_MAX, bhy = -FLT_MAX,
          blz = FLT_MAX, bhz = -FLT_MAX;
#pragma unroll
    for (int i = 0; i < 8; i++) {
        int o0 = sOrd[wbase + i * 64], o1 = sOrd[wbase + i * 64 + 1];
        ordp[i] = (unsigned)o0 | ((unsigned)o1 << 16);
        float4 a = sP[o0], c = sP[o1];
        X[i] = pk2(a.x, c.x); Y[i] = pk2(a.y, c.y); Z[i] = pk2(a.z, c.z);
        blx = fminf(blx, fminf(a.x, c.x)); bhx = fmaxf(bhx, fmaxf(a.x, c.x));
        bly = fminf(bly, fminf(a.y, c.y)); bhy = fmaxf(bhy, fmaxf(a.y, c.y));
        blz = fminf(blz, fminf(a.z, c.z)); bhz = fmaxf(bhz, fmaxf(a.z, c.z));
    }
#pragma unroll
    for (int s = 16; s > 0; s >>= 1) {
        blx = fminf(blx, __shfl_xor_sync(0xffffffffu, blx, s));
        bhx = fmaxf(bhx, __shfl_xor_sync(0xffffffffu, bhx, s));
        bly = fminf(bly, __shfl_xor_sync(0xffffffffu, bly, s));
        bhy = fmaxf(bhy, __shfl_xor_sync(0xffffffffu, bhy, s));
        blz = fminf(blz, __shfl_xor_sync(0xffffffffu, blz, s));
        bhz = fmaxf(bhz, __shfl_xor_sync(0xffffffffu, bhz, s));
    }

    u64 mykey;
    float wmaxf;
    {   // iteration 0: d0 = ||x - x0||^2
        float4 q0 = sP[0];
        u64 ax = pk2(-q0.x, -q0.x), ay = pk2(-q0.y, -q0.y), az = pk2(-q0.z, -q0.z);
#pragma unroll
        for (int i = 0; i < 8; i++) {
            u64 dx = add2(X[i], ax), dy = add2(Y[i], ay), dz = add2(Z[i], az);
            u64 t = fma2(dz, dz, fma2(dy, dy, mul2(dx, dx)));
            upk2(t, dist[2 * i], dist[2 * i + 1]);
        }
        float tmax = dist[0];
#pragma unroll
        for (int k = 1; k < 16; k++) tmax = fmaxf(tmax, dist[k]);
        unsigned wm = __reduce_max_sync(0xffffffffu, __float_as_uint(tmax));
        wmaxf = __uint_as_float(wm);
        unsigned cand = 0xffffffffu;
#pragma unroll
        for (int k = 0; k < 16; k++) {
            unsigned oi = (k & 1) ? (ordp[k >> 1] >> 16) : (ordp[k >> 1] & 0xffffu);
            if (dist[k] == wmaxf) cand = min(cand, oi);
        }
        unsigned widx = __reduce_min_sync(0xffffffffu, cand);
        mykey = ((u64)wm << 32) | widx;
        if (lane == 0) skey[0][wid] = mykey;
    }

    for (int j = 1; j < NPQ; j++) {
        __syncthreads();                               // prev-iter keys visible
        u64 k64 = skey[(j - 1) & 1][lane & 15];        // halves duplicated -> same result
        unsigned hi = (unsigned)(k64 >> 32), lo = (unsigned)k64;
        unsigned g   = __reduce_max_sync(0xffffffffu, hi);
        unsigned cc  = (hi == g) ? lo : 0xffffffffu;
        unsigned nxt = __reduce_min_sync(0xffffffffu, cc);
        if (tid == 0) g_fps[b * NPQ + j] = (int)nxt;

        float4 qq = sP[nxt];                           // LDS broadcast
        float dxb = fmaxf(fmaxf(blx - qq.x, qq.x - bhx), 0.f);
        float dyb = fmaxf(fmaxf(bly - qq.y, qq.y - bhy), 0.f);
        float dzb = fmaxf(fmaxf(blz - qq.z, qq.z - bhz), 0.f);
        float boxd2 = __fmaf_rn(dzb, dzb, __fmaf_rn(dyb, dyb, dxb * dxb));

        if (boxd2 < wmaxf * 1.00001f) {                // conservative: update
            u64 ax = pk2(-qq.x, -qq.x), ay = pk2(-qq.y, -qq.y), az = pk2(-qq.z, -qq.z);
#pragma unroll
            for (int i = 0; i < 8; i++) {
                u64 dx = add2(X[i], ax), dy = add2(Y[i], ay), dz = add2(Z[i], az);
                u64 t = fma2(dz, dz, fma2(dy, dy, mul2(dx, dx)));
                float a, c; upk2(t, a, c);
                dist[2 * i]     = fminf(dist[2 * i], a);
                dist[2 * i + 1] = fminf(dist[2 * i + 1], c);
            }
            float tmax = dist[0];
#pragma unroll
            for (int k = 1; k < 16; k++) tmax = fmaxf(tmax, dist[k]);
            unsigned wm = __reduce_max_sync(0xffffffffu, __float_as_uint(tmax));
            wmaxf = __uint_as_float(wm);
            unsigned cand = 0xffffffffu;
#pragma unroll
            for (int k = 0; k < 16; k++) {
                unsigned oi = (k & 1) ? (ordp[k >> 1] >> 16) : (ordp[k >> 1] & 0xffffu);
                if (dist[k] == wmaxf) cand = min(cand, oi);
            }
            unsigned widx = __reduce_min_sync(0xffffffffu, cand);
            mykey = ((u64)wm << 32) | widx;
        }
        if (lane == 0) skey[j & 1][wid] = mykey;       // always post
    }
}

// ---------------- gather sampled coords ----------------
__global__ void gather_q4_kernel() {
    int i = blockIdx.x * 256 + threadIdx.x;          // over NB*NPQ
    int b = i >> 11;
    g_q4[i] = g_p4[b * NPTS + g_fps[i]];
}

// ---------------- kNN: warp-shared sorted top-17 + mean-pool ----------------
__global__ void __launch_bounds__(256) knn_group_kernel() {
    extern __shared__ float4 sT[];                    // 8192 float4 = 128KB
    const int tid  = threadIdx.x;
    const int lane = tid & 31;
    const int w    = tid >> 5;
    const int b    = blockIdx.x >> 5;
    const int qb   = (blockIdx.x & 31) * 64;

#pragma unroll
    for (int k = 0; k < 32; k++) sT[tid + k * 256] = g_p4[b * NPTS + tid + k * 256];
    __syncthreads();

    const float* Fb = g_feat_t + (size_t)b * NPTS * NCH;
    for (int qi = 0; qi < 8; qi++) {
        int gw = b * NPQ + qb + w * 8 + qi;
        float4 q = g_q4[gw];
        u64 mykey = ~0ull, thr = ~0ull;
        for (int t = 0; t < NPTS / 32; t++) {
            int n = t * 32 + lane;
            float4 p = sT[n];
            float dot = __fmaf_rn(q.z, p.z, __fmaf_rn(q.y, p.y, q.x * p.x));
            float sq  = fmaxf(__fmaf_rn(-2.f, dot, q.w + p.w), 0.f);
            u64 cand = ((u64)__float_as_uint(sq) << 32) | (unsigned)n;
            unsigned ball = __ballot_sync(0xffffffffu, cand < thr);
            while (ball) {
                int src = __ffs(ball) - 1; ball &= ball - 1;
                u64 c = __shfl_sync(0xffffffffu, cand, src);
                unsigned pb = __ballot_sync(0xffffffffu, (lane < 17) && (c < mykey));
                if (pb) {
                    int pos = __ffs(pb) - 1;
                    u64 up = __shfl_up_sync(0xffffffffu, mykey, 1);
                    if (lane >= pos && lane < 17) mykey = (lane == pos) ? c : up;
                }
                thr = __shfl_sync(0xffffffffu, mykey, 16);
            }
        }
        float4 acc = make_float4(0.f, 0.f, 0.f, 0.f);
#pragma unroll 1
        for (int r = 1; r < 17; r++) {
            int nn = (int)(unsigned)__shfl_sync(0xffffffffu, mykey, r);
            float4 f = ((const float4*)(Fb + (size_t)nn * NCH))[lane];
            acc.x += f.x; acc.y += f.y; acc.z += f.z; acc.w += f.w;
        }
        float4 o = make_float4(acc.x * 0.0625f, acc.y * 0.0625f,
                               acc.z * 0.0625f, acc.w * 0.0625f);
        ((float4*)(g_coarse_t + (size_t)gw * NCH))[lane] = o;
    }
}

// ---------------- three_nn part: each chunk of 512 queries -> 3 lex keys ----------------
__global__ void __launch_bounds__(256) three_nn_part() {
    int b = blockIdx.y, c = blockIdx.z;
    int n = blockIdx.x * 256 + threadIdx.x;
    __shared__ float4 sq4[512];
    for (int i = threadIdx.x; i < 512; i += 256) sq4[i] = g_q4[b * NPQ + c * 512 + i];
    __syncthreads();

    float4 p = g_p4[b * NPTS + n];
    float d0 = FLT_MAX, d1 = FLT_MAX, d2 = FLT_MAX;
    int   i0 = 0, i1 = 0, i2 = 0;
    for (int j2 = 0; j2 < 512; j2++) {
        float4 q = sq4[j2];
        int j = c * 512 + j2;
        float dot = __fmaf_rn(q.z, p.z, __fmaf_rn(q.y, p.y, q.x * p.x));
        float s   = fmaxf(__fmaf_rn(-2.f, dot, q.w + p.w), 0.f);
        bool c2 = s < d2, c1 = s < d1, c0 = s < d0;
        d2 = c1 ? d1 : (c2 ? s : d2);
        i2 = c1 ? i1 : (c2 ? j : i2);
        d1 = c0 ? d0 : (c1 ? s : d1);
        i1 = c0 ? i0 : (c1 ? j : i1);
        d0 = c0 ? s : d0;
        i0 = c0 ? j : i0;
    }
    size_t o = ((size_t)(b * NPTS + n) * 4 + c) * 3;
    g_nn[o]     = ((u64)__float_as_uint(d0) << 32) | (unsigned)i0;
    g_nn[o + 1] = ((u64)__float_as_uint(d1) << 32) | (unsigned)i1;
    g_nn[o + 2] = ((u64)__float_as_uint(d2) << 32) | (unsigned)i2;
}

// ---------------- three_nn combine: merge 4 chunks, compute weights ----------------
__global__ void __launch_bounds__(256) three_nn_comb() {
    int i = blockIdx.x * 256 + threadIdx.x;           // over NB*NPTS
    u64 a0 = ~0ull, a1 = ~0ull, a2 = ~0ull;
#pragma unroll
    for (int c = 0; c < 12; c++) {
        u64 k = g_nn[(size_t)i * 12 + c];
        if (k < a0)      { a2 = a1; a1 = a0; a0 = k; }
        else if (k < a1) { a2 = a1; a1 = k; }
        else if (k < a2) { a2 = k; }
    }
    float d0 = fmaxf(__uint_as_float((unsigned)(a0 >> 32)), 1e-10f);
    float d1 = fmaxf(__uint_as_float((unsigned)(a1 >> 32)), 1e-10f);
    float d2 = fmaxf(__uint_as_float((unsigned)(a2 >> 32)), 1e-10f);
    float v0 = __fdiv_rn(1.f, d0 + 1e-8f);
    float v1 = __fdiv_rn(1.f, d1 + 1e-8f);
    float v2 = __fdiv_rn(1.f, d2 + 1e-8f);
    float ss = v0 + v1 + v2;
    int o = i * 3;
    g_i3[o] = (int)(unsigned)a0; g_i3[o + 1] = (int)(unsigned)a1; g_i3[o + 2] = (int)(unsigned)a2;
    g_w3[o]     = __fdiv_rn(v0, ss);
    g_w3[o + 1] = __fdiv_rn(v1, ss);
    g_w3[o + 2] = __fdiv_rn(v2, ss);
}

// ---------------- interpolate: out[b,c,n] = sum_k w_k * coarse[b, i3_k, c] ----------------
__global__ void __launch_bounds__(256) interp_kernel(float* __restrict__ out) {
    int b    = blockIdx.y;
    int n    = blockIdx.x * 8 + threadIdx.y;
    int lane = threadIdx.x;
    int o = (b * NPTS + n) * 3;
    int a0 = g_i3[o], a1 = g_i3[o + 1], a2 = g_i3[o + 2];
    float w0 = g_w3[o], w1 = g_w3[o + 1], w2 = g_w3[o + 2];

    const float4* C = (const float4*)g_coarse_t + (size_t)b * NPQ * (NCH / 4);
    float4 f0 = C[a0 * (NCH / 4) + lane];
    float4 f1 = C[a1 * (NCH / 4) + lane];
    float4 f2 = C[a2 * (NCH / 4) + lane];

    float4 r;
    r.x = __fmaf_rn(f2.x, w2, __fmaf_rn(f1.x, w1, f0.x * w0));
    r.y = __fmaf_rn(f2.y, w2, __fmaf_rn(f1.y, w1, f0.y * w0));
    r.z = __fmaf_rn(f2.z, w2, __fmaf_rn(f1.z, w1, f0.z * w0));
    r.w = __fmaf_rn(f2.w, w2, __fmaf_rn(f1.w, w1, f0.w * w0));

    float* op = out + (size_t)b * NCH * NPTS + n;
    int c = lane * 4;
    op[(size_t)(c + 0) * NPTS] = r.x;
    op[(size_t)(c + 1) * NPTS] = r.y;
    op[(size_t)(c + 2) * NPTS] = r.z;
    op[(size_t)(c + 3) * NPTS] = r.w;
}

// ---------------- launch ----------------
extern "C" void kernel_launch(void* const* d_in, const int* in_sizes, int n_in,
                              void* d_out, int out_size) {
    const float* points   = (const float*)d_in[0];
    const float* features = (const float*)d_in[1];
    for (int i = 0; i < n_in; i++) {
        if (in_sizes[i] == NB * NPTS * 3)            points   = (const float*)d_in[i];
        else if (in_sizes[i] == NB * NCH * NPTS)     features = (const float*)d_in[i];
    }
    float* out = (float*)d_out;

    const int fps_smem = NPTS * (int)sizeof(float4) + NPTS * (int)sizeof(int); // 160KB
    const int knn_smem = NPTS * (int)sizeof(float4);                           // 128KB
    cudaFuncSetAttribute(fps_kernel,       cudaFuncAttributeMaxDynamicSharedMemorySize, fps_smem);
    cudaFuncSetAttribute(knn_group_kernel, cudaFuncAttributeMaxDynamicSharedMemorySize, knn_smem);

    prep_kernel<<<(NB * NPTS) / 256, 256>>>(points);
    transpose_kernel<<<dim3(NPTS / 32, NCH / 32, NB), dim3(32, 32)>>>(features);
    sort_kernel<<<NB, 1024>>>();
    fps_kernel<<<NB, 512, fps_smem>>>();
    gather_q4_kernel<<<(NB * NPQ) / 256, 256>>>();
    knn_group_kernel<<<128, 256, knn_smem>>>();
    three_nn_part<<<dim3(NPTS / 256, NB, 4), 256>>>();
    three_nn_comb<<<(NB * NPTS) / 256, 256>>>();
    interp_kernel<<<dim3(NPTS / 8, NB), dim3(32, 8)>>>(out);
}

// round 12
// speedup vs baseline: 1.2171x; 1.0035x over previous
#include <cuda_runtime.h>
#include <cstdint>
#include <float.h>

#define NB    4
#define NPTS  8192
#define NPQ   2048
#define NCH   128

// ---------------- device scratch (statically allocated; no cudaMalloc) ----------------
__device__ float4 g_p4[NB * NPTS];                    // (x,y,z,|p|^2)
__device__ float4 g_q4[NB * NPQ];                     // sampled points
__device__ int    g_fps[NB * NPQ];
__device__ int    g_ord[NB * NPTS];                   // morton-binned original indices
__device__ float  g_feat_t[(size_t)NB * NPTS * NCH];  // features transposed [B,N,C]
__device__ float  g_coarse_t[(size_t)NB * NPQ * NCH]; // pooled features [B,q,C]
__device__ int    g_i3[NB * NPTS * 3];
__device__ float  g_w3[NB * NPTS * 3];

typedef unsigned long long u64;
__device__ u64 g_nn[(size_t)NB * NPTS * 12];          // three_nn partials: 4 chunks x 3 keys

// ---------------- packed f32x2 helpers ----------------
__device__ __forceinline__ u64 pk2(float a, float b) {
    u64 r; asm("mov.b64 %0, {%1,%2};" : "=l"(r) : "f"(a), "f"(b)); return r;
}
__device__ __forceinline__ void upk2(u64 v, float& a, float& b) {
    asm("mov.b64 {%0,%1}, %2;" : "=f"(a), "=f"(b) : "l"(v));
}
__device__ __forceinline__ u64 add2(u64 a, u64 b) {
    u64 r; asm("add.rn.f32x2 %0, %1, %2;" : "=l"(r) : "l"(a), "l"(b)); return r;
}
__device__ __forceinline__ u64 mul2(u64 a, u64 b) {
    u64 r; asm("mul.rn.f32x2 %0, %1, %2;" : "=l"(r) : "l"(a), "l"(b)); return r;
}
__device__ __forceinline__ u64 fma2(u64 a, u64 b, u64 c) {
    u64 r; asm("fma.rn.f32x2 %0, %1, %2, %3;" : "=l"(r) : "l"(a), "l"(b), "l"(c)); return r;
}

// ---------------- prep: pack points + squared norm ----------------
__global__ void prep_kernel(const float* __restrict__ pts) {
    int i = blockIdx.x * 256 + threadIdx.x;          // over NB*NPTS
    float x = pts[3 * i], y = pts[3 * i + 1], z = pts[3 * i + 2];
    float nr = __fmaf_rn(z, z, __fmaf_rn(y, y, x * x));
    g_p4[i] = make_float4(x, y, z, nr);
}

// ---------------- transpose features [B,C,N] -> [B,N,C] ----------------
__global__ void transpose_kernel(const float* __restrict__ f) {
    __shared__ float tile[32][33];
    int b = blockIdx.z;
    int c0 = blockIdx.y * 32, n0 = blockIdx.x * 32;
    tile[threadIdx.y][threadIdx.x] =
        f[((size_t)b * NCH + c0 + threadIdx.y) * NPTS + n0 + threadIdx.x];
    __syncthreads();
    g_feat_t[((size_t)b * NPTS + n0 + threadIdx.y) * NCH + c0 + threadIdx.x] =
        tile[threadIdx.x][threadIdx.y];
}

// ---------------- morton binning: counting sort into 4096 cells (16^3) ----------------
__device__ __forceinline__ unsigned eb4(unsigned v) {  // 4 bits -> stride-3 positions
    return (v & 1u) | ((v & 2u) << 2) | ((v & 4u) << 4) | ((v & 8u) << 6);
}
__global__ void __launch_bounds__(1024, 1) sort_kernel() {
    __shared__ unsigned hist[4096];
    __shared__ unsigned wsum[32];
    const int b = blockIdx.x, tid = threadIdx.x;
    const int lane = tid & 31, wid = tid >> 5;
    for (int i = tid; i < 4096; i += 1024) hist[i] = 0;
    __syncthreads();
    unsigned code[8];
#pragma unroll
    for (int k = 0; k < 8; k++) {
        int i = tid + k * 1024;
        float4 p = g_p4[b * NPTS + i];
        unsigned mx = (unsigned)fminf(fmaxf((p.x + 4.f) * 2.f, 0.f), 15.f);
        unsigned my = (unsigned)fminf(fmaxf((p.y + 4.f) * 2.f, 0.f), 15.f);
        unsigned mz = (unsigned)fminf(fmaxf((p.z + 4.f) * 2.f, 0.f), 15.f);
        code[k] = eb4(mx) | (eb4(my) << 1) | (eb4(mz) << 2);
        atomicAdd(&hist[code[k]], 1u);
    }
    __syncthreads();
    unsigned h0 = hist[4 * tid], h1 = hist[4 * tid + 1],
             h2 = hist[4 * tid + 2], h3 = hist[4 * tid + 3];
    unsigned s = h0 + h1 + h2 + h3, si = s;
#pragma unroll
    for (int d = 1; d < 32; d <<= 1) {
        unsigned v = __shfl_up_sync(0xffffffffu, si, d);
        if (lane >= d) si += v;
    }
    if (lane == 31) wsum[wid] = si;
    __syncthreads();
    if (wid == 0) {
        unsigned v = wsum[lane], vi = v;
#pragma unroll
        for (int d = 1; d < 32; d <<= 1) {
            unsigned t = __shfl_up_sync(0xffffffffu, vi, d);
            if (lane >= d) vi += t;
        }
        wsum[lane] = vi;
    }
    __syncthreads();
    unsigned base = (wid ? wsum[wid - 1] : 0u) + si - s;
    hist[4 * tid]     = base;
    hist[4 * tid + 1] = base + h0;
    hist[4 * tid + 2] = base + h0 + h1;
    hist[4 * tid + 3] = base + h0 + h1 + h2;
    __syncthreads();
#pragma unroll
    for (int k = 0; k < 8; k++) {
        int i = tid + k * 1024;
        unsigned slot = atomicAdd(&hist[code[k]], 1u);
        g_ord[b * NPTS + slot] = i;
    }
}

// ---------------- FPS: one CTA/batch, 512 threads x 16 pts, warp pruning ----------------
// (unchanged from R11: at the serial-latency floor) Update math = reference's
// EXACT subtract-form fma chain (frozen). Tie rule = lowest original index.
__global__ void __launch_bounds__(512, 1) fps_kernel() {
    extern __shared__ char fsmem[];                   // sP 128KB | sOrd 32KB
    float4* sP   = (float4*)fsmem;
    int*    sOrd = (int*)(fsmem + NPTS * sizeof(float4));
    const int b    = blockIdx.x;
    const int tid  = threadIdx.x;
    const int lane = tid & 31;
    const int wid  = tid >> 5;                        // 0..15
    const float4* __restrict__ P = g_p4 + b * NPTS;

#pragma unroll
    for (int k = 0; k < 16; k++) {
        sP[tid + k * 512]   = P[tid + k * 512];
        sOrd[tid + k * 512] = g_ord[b * NPTS + tid + k * 512];
    }
    __shared__ u64 skey[2][16];
    if (tid == 0) g_fps[b * NPQ] = 0;
    __syncthreads();

    const int wbase = wid * 512 + lane * 2;
    u64 X[8], Y[8], Z[8];
    float dist[16];
    unsigned ordp[8];
    float blx = FLT_MAX, bhx = -FLT_MAX, bly = FLT_MAX, bhy = -FLT_MAX,
          blz = FLT_MAX, bhz = -FLT_MAX;
#pragma unroll
    for (int i = 0; i < 8; i++) {
        int o0 = sOrd[wbase + i * 64], o1 = sOrd[wbase + i * 64 + 1];
        ordp[i] = (unsigned)o0 | ((unsigned)o1 << 16);
        float4 a = sP[o0], c = sP[o1];
        X[i] = pk2(a.x, c.x); Y[i] = pk2(a.y, c.y); Z[i] = pk2(a.z, c.z);
        blx = fminf(blx, fminf(a.x, c.x)); bhx = fmaxf(bhx, fmaxf(a.x, c.x));
        bly = fminf(bly, fminf(a.y, c.y)); bhy = fmaxf(bhy, fmaxf(a.y, c.y));
        blz = fminf(blz, fminf(a.z, c.z)); bhz = fmaxf(bhz, fmaxf(a.z, c.z));
    }
#pragma unroll
    for (int s = 16; s > 0; s >>= 1) {
        blx = fminf(blx, __shfl_xor_sync(0xffffffffu, blx, s));
        bhx = fmaxf(bhx, __shfl_xor_sync(0xffffffffu, bhx, s));
        bly = fminf(bly, __shfl_xor_sync(0xffffffffu, bly, s));
        bhy = fmaxf(bhy, __shfl_xor_sync(0xffffffffu, bhy, s));
        blz = fminf(blz, __shfl_xor_sync(0xffffffffu, blz, s));
        bhz = fmaxf(bhz, __shfl_xor_sync(0xffffffffu, bhz, s));
    }

    u64 mykey;
    float wmaxf;
    {   // iteration 0: d0 = ||x - x0||^2
        float4 q0 = sP[0];
        u64 ax = pk2(-q0.x, -q0.x), ay = pk2(-q0.y, -q0.y), az = pk2(-q0.z, -q0.z);
#pragma unroll
        for (int i = 0; i < 8; i++) {
            u64 dx = add2(X[i], ax), dy = add2(Y[i], ay), dz = add2(Z[i], az);
            u64 t = fma2(dz, dz, fma2(dy, dy, mul2(dx, dx)));
            upk2(t, dist[2 * i], dist[2 * i + 1]);
        }
        float tmax = dist[0];
#pragma unroll
        for (int k = 1; k < 16; k++) tmax = fmaxf(tmax, dist[k]);
        unsigned wm = __reduce_max_sync(0xffffffffu, __float_as_uint(tmax));
        wmaxf = __uint_as_float(wm);
        unsigned cand = 0xffffffffu;
#pragma unroll
        for (int k = 0; k < 16; k++) {
            unsigned oi = (k & 1) ? (ordp[k >> 1] >> 16) : (ordp[k >> 1] & 0xffffu);
            if (dist[k] == wmaxf) cand = min(cand, oi);
        }
        unsigned widx = __reduce_min_sync(0xffffffffu, cand);
        mykey = ((u64)wm << 32) | widx;
        if (lane == 0) skey[0][wid] = mykey;
    }

    for (int j = 1; j < NPQ; j++) {
        __syncthreads();
        u64 k64 = skey[(j - 1) & 1][lane & 15];
        unsigned hi = (unsigned)(k64 >> 32), lo = (unsigned)k64;
        unsigned g   = __reduce_max_sync(0xffffffffu, hi);
        unsigned cc  = (hi == g) ? lo : 0xffffffffu;
        unsigned nxt = __reduce_min_sync(0xffffffffu, cc);
        if (tid == 0) g_fps[b * NPQ + j] = (int)nxt;

        float4 qq = sP[nxt];
        float dxb = fmaxf(fmaxf(blx - qq.x, qq.x - bhx), 0.f);
        float dyb = fmaxf(fmaxf(bly - qq.y, qq.y - bhy), 0.f);
        float dzb = fmaxf(fmaxf(blz - qq.z, qq.z - bhz), 0.f);
        float boxd2 = __fmaf_rn(dzb, dzb, __fmaf_rn(dyb, dyb, dxb * dxb));

        if (boxd2 < wmaxf * 1.00001f) {
            u64 ax = pk2(-qq.x, -qq.x), ay = pk2(-qq.y, -qq.y), az = pk2(-qq.z, -qq.z);
#pragma unroll
            for (int i = 0; i < 8; i++) {
                u64 dx = add2(X[i], ax), dy = add2(Y[i], ay), dz = add2(Z[i], az);
                u64 t = fma2(dz, dz, fma2(dy, dy, mul2(dx, dx)));
                float a, c; upk2(t, a, c);
                dist[2 * i]     = fminf(dist[2 * i], a);
                dist[2 * i + 1] = fminf(dist[2 * i + 1], c);
            }
            float tmax = dist[0];
#pragma unroll
            for (int k = 1; k < 16; k++) tmax = fmaxf(tmax, dist[k]);
            unsigned wm = __reduce_max_sync(0xffffffffu, __float_as_uint(tmax));
            wmaxf = __uint_as_float(wm);
            unsigned cand = 0xffffffffu;
#pragma unroll
            for (int k = 0; k < 16; k++) {
                unsigned oi = (k & 1) ? (ordp[k >> 1] >> 16) : (ordp[k >> 1] & 0xffffu);
                if (dist[k] == wmaxf) cand = min(cand, oi);
            }
            unsigned widx = __reduce_min_sync(0xffffffffu, cand);
            mykey = ((u64)wm << 32) | widx;
        }
        if (lane == 0) skey[j & 1][wid] = mykey;
    }
}

// ---------------- gather sampled coords ----------------
__global__ void gather_q4_kernel() {
    int i = blockIdx.x * 256 + threadIdx.x;          // over NB*NPQ
    int b = i >> 11;
    g_q4[i] = g_p4[b * NPTS + g_fps[i]];
}

// ---------------- kNN: warp-shared sorted top-17 + mean-pool (MLP=4 gather) ----------------
__global__ void __launch_bounds__(256) knn_group_kernel() {
    extern __shared__ float4 sT[];                    // 8192 float4 = 128KB
    const int tid  = threadIdx.x;
    const int lane = tid & 31;
    const int w    = tid >> 5;
    const int b    = blockIdx.x >> 5;
    const int qb   = (blockIdx.x & 31) * 64;

#pragma unroll
    for (int k = 0; k < 32; k++) sT[tid + k * 256] = g_p4[b * NPTS + tid + k * 256];
    __syncthreads();

    const float* Fb = g_feat_t + (size_t)b * NPTS * NCH;
    for (int qi = 0; qi < 8; qi++) {
        int gw = b * NPQ + qb + w * 8 + qi;
        float4 q = g_q4[gw];
        u64 mykey = ~0ull, thr = ~0ull;
        for (int t = 0; t < NPTS / 32; t++) {
            int n = t * 32 + lane;
            float4 p = sT[n];
            float dot = __fmaf_rn(q.z, p.z, __fmaf_rn(q.y, p.y, q.x * p.x));
            float sq  = fmaxf(__fmaf_rn(-2.f, dot, q.w + p.w), 0.f);
            u64 cand = ((u64)__float_as_uint(sq) << 32) | (unsigned)n;
            unsigned ball = __ballot_sync(0xffffffffu, cand < thr);
            while (ball) {
                int src = __ffs(ball) - 1; ball &= ball - 1;
                u64 c = __shfl_sync(0xffffffffu, cand, src);
                unsigned pb = __ballot_sync(0xffffffffu, (lane < 17) && (c < mykey));
                if (pb) {
                    int pos = __ffs(pb) - 1;
                    u64 up = __shfl_up_sync(0xffffffffu, mykey, 1);
                    if (lane >= pos && lane < 17) mykey = (lane == pos) ? c : up;
                }
                thr = __shfl_sync(0xffffffffu, mykey, 16);
            }
        }
        // mean-pool: 16 neighbor rows in ascending-distance order; loads batched
        // (MLP=4) but additions remain in the exact same sequential order.
        float4 acc = make_float4(0.f, 0.f, 0.f, 0.f);
#pragma unroll
        for (int r = 1; r < 17; r += 4) {
            int n0 = (int)(unsigned)__shfl_sync(0xffffffffu, mykey, r);
            int n1 = (int)(unsigned)__shfl_sync(0xffffffffu, mykey, r + 1);
            int n2 = (int)(unsigned)__shfl_sync(0xffffffffu, mykey, r + 2);
            int n3 = (int)(unsigned)__shfl_sync(0xffffffffu, mykey, r + 3);
            float4 f0 = ((const float4*)(Fb + (size_t)n0 * NCH))[lane];
            float4 f1 = ((const float4*)(Fb + (size_t)n1 * NCH))[lane];
            float4 f2 = ((const float4*)(Fb + (size_t)n2 * NCH))[lane];
            float4 f3 = ((const float4*)(Fb + (size_t)n3 * NCH))[lane];
            acc.x += f0.x; acc.y += f0.y; acc.z += f0.z; acc.w += f0.w;
            acc.x += f1.x; acc.y += f1.y; acc.z += f1.z; acc.w += f1.w;
            acc.x += f2.x; acc.y += f2.y; acc.z += f2.z; acc.w += f2.w;
            acc.x += f3.x; acc.y += f3.y; acc.z += f3.z; acc.w += f3.w;
        }
        float4 o = make_float4(acc.x * 0.0625f, acc.y * 0.0625f,
                               acc.z * 0.0625f, acc.w * 0.0625f);
        ((float4*)(g_coarse_t + (size_t)gw * NCH))[lane] = o;
    }
}

// ---------------- three_nn part: each chunk of 512 queries -> 3 lex keys ----------------
__global__ void __launch_bounds__(256) three_nn_part() {
    int b = blockIdx.y, c = blockIdx.z;
    int n = blockIdx.x * 256 + threadIdx.x;
    __shared__ float4 sq4[512];
    for (int i = threadIdx.x; i < 512; i += 256) sq4[i] = g_q4[b * NPQ + c * 512 + i];
    __syncthreads();

    float4 p = g_p4[b * NPTS + n];
    float d0 = FLT_MAX, d1 = FLT_MAX, d2 = FLT_MAX;
    int   i0 = 0, i1 = 0, i2 = 0;
    for (int j2 = 0; j2 < 512; j2++) {
        float4 q = sq4[j2];
        int j = c * 512 + j2;
        float dot = __fmaf_rn(q.z, p.z, __fmaf_rn(q.y, p.y, q.x * p.x));
        float s   = fmaxf(__fmaf_rn(-2.f, dot, q.w + p.w), 0.f);
        bool c2 = s < d2, c1 = s < d1, c0 = s < d0;
        d2 = c1 ? d1 : (c2 ? s : d2);
        i2 = c1 ? i1 : (c2 ? j : i2);
        d1 = c0 ? d0 : (c1 ? s : d1);
        i1 = c0 ? i0 : (c1 ? j : i1);
        d0 = c0 ? s : d0;
        i0 = c0 ? j : i0;
    }
    size_t o = ((size_t)(b * NPTS + n) * 4 + c) * 3;
    g_nn[o]     = ((u64)__float_as_uint(d0) << 32) | (unsigned)i0;
    g_nn[o + 1] = ((u64)__float_as_uint(d1) << 32) | (unsigned)i1;
    g_nn[o + 2] = ((u64)__float_as_uint(d2) << 32) | (unsigned)i2;
}

// ---------------- three_nn combine: merge 4 chunks, compute weights ----------------
__global__ void __launch_bounds__(256) three_nn_comb() {
    int i = blockIdx.x * 256 + threadIdx.x;           // over NB*NPTS
    u64 a0 = ~0ull, a1 = ~0ull, a2 = ~0ull;
#pragma unroll
    for (int c = 0; c < 12; c++) {
        u64 k = g_nn[(size_t)i * 12 + c];
        if (k < a0)      { a2 = a1; a1 = a0; a0 = k; }
        else if (k < a1) { a2 = a1; a1 = k; }
        else if (k < a2) { a2 = k; }
    }
    float d0 = fmaxf(__uint_as_float((unsigned)(a0 >> 32)), 1e-10f);
    float d1 = fmaxf(__uint_as_float((unsigned)(a1 >> 32)), 1e-10f);
    float d2 = fmaxf(__uint_as_float((unsigned)(a2 >> 32)), 1e-10f);
    float v0 = __fdiv_rn(1.f, d0 + 1e-8f);
    float v1 = __fdiv_rn(1.f, d1 + 1e-8f);
    float v2 = __fdiv_rn(1.f, d2 + 1e-8f);
    float ss = v0 + v1 + v2;
    int o = i * 3;
    g_i3[o] = (int)(unsigned)a0; g_i3[o + 1] = (int)(unsigned)a1; g_i3[o + 2] = (int)(unsigned)a2;
    g_w3[o]     = __fdiv_rn(v0, ss);
    g_w3[o + 1] = __fdiv_rn(v1, ss);
    g_w3[o + 2] = __fdiv_rn(v2, ss);
}

// ---------------- interpolate: smem-staged, coalesced channel-major stores ----------------
// Phase 1: 8 warps x 4 n each compute r into a 32n x 128c smem tile (pitch 129).
// Phase 2: for each channel, 32 consecutive n are written as one 128B run.
// Values identical to prior version; only the store pattern changed.
__global__ void __launch_bounds__(256) interp_kernel(float* __restrict__ out) {
    __shared__ float tile[32 * 129];
    int b    = blockIdx.y;
    int n0   = blockIdx.x * 32;
    int lane = threadIdx.x & 31;                      // float4-channel group
    int w    = threadIdx.x >> 5;

#pragma unroll
    for (int k = 0; k < 4; k++) {
        int nl = w * 4 + k;                           // local n 0..31
        int n  = n0 + nl;
        int o = (b * NPTS + n) * 3;
        int a0 = g_i3[o], a1 = g_i3[o + 1], a2 = g_i3[o + 2];
        float w0 = g_w3[o], w1 = g_w3[o + 1], w2 = g_w3[o + 2];

        const float4* C = (const float4*)g_coarse_t + (size_t)b * NPQ * (NCH / 4);
        float4 f0 = C[a0 * (NCH / 4) + lane];
        float4 f1 = C[a1 * (NCH / 4) + lane];
        float4 f2 = C[a2 * (NCH / 4) + lane];

        float4 r;
        r.x = __fmaf_rn(f2.x, w2, __fmaf_rn(f1.x, w1, f0.x * w0));
        r.y = __fmaf_rn(f2.y, w2, __fmaf_rn(f1.y, w1, f0.y * w0));
        r.z = __fmaf_rn(f2.z, w2, __fmaf_rn(f1.z, w1, f0.z * w0));
        r.w = __fmaf_rn(f2.w, w2, __fmaf_rn(f1.w, w1, f0.w * w0));

        float* trow = tile + nl * 129 + lane * 4;
        trow[0] = r.x; trow[1] = r.y; trow[2] = r.z; trow[3] = r.w;
    }
    __syncthreads();

    float* ob = out + (size_t)b * NCH * NPTS + n0;
#pragma unroll
    for (int pass = 0; pass < 16; pass++) {
        int c = pass * 8 + w;                         // channel
        ob[(size_t)c * NPTS + lane] = tile[lane * 129 + c];
    }
}

// ---------------- launch ----------------
extern "C" void kernel_launch(void* const* d_in, const int* in_sizes, int n_in,
                              void* d_out, int out_size) {
    const float* points   = (const float*)d_in[0];
    const float* features = (const float*)d_in[1];
    for (int i = 0; i < n_in; i++) {
        if (in_sizes[i] == NB * NPTS * 3)            points   = (const float*)d_in[i];
        else if (in_sizes[i] == NB * NCH * NPTS)     features = (const float*)d_in[i];
    }
    float* out = (float*)d_out;

    const int fps_smem = NPTS * (int)sizeof(float4) + NPTS * (int)sizeof(int); // 160KB
    const int knn_smem = NPTS * (int)sizeof(float4);                           // 128KB
    cudaFuncSetAttribute(fps_kernel,       cudaFuncAttributeMaxDynamicSharedMemorySize, fps_smem);
    cudaFuncSetAttribute(knn_group_kernel, cudaFuncAttributeMaxDynamicSharedMemorySize, knn_smem);

    prep_kernel<<<(NB * NPTS) / 256, 256>>>(points);
    transpose_kernel<<<dim3(NPTS / 32, NCH / 32, NB), dim3(32, 32)>>>(features);
    sort_kernel<<<NB, 1024>>>();
    fps_kernel<<<NB, 512, fps_smem>>>();
    gather_q4_kernel<<<(NB * NPQ) / 256, 256>>>();
    knn_group_kernel<<<128, 256, knn_smem>>>();
    three_nn_part<<<dim3(NPTS / 256, NB, 4), 256>>>();
    three_nn_comb<<<(NB * NPTS) / 256, 256>>>();
    interp_kernel<<<dim3(NPTS / 32, NB), 256>>>(out);
}